// round 12
// baseline (speedup 1.0000x reference)
#include <cuda_runtime.h>
#include <math.h>

// Problem constants (fixed by the dataset)
#define NQTOT  7200      // B*N = 8*900
#define NQPAD  7296      // padded to multiple of 128 for k2 tiles
#define NPERB  900
#define CDIM   256
#define HEADS  8
#define NPTS   4
#define BEV    200
#define HW     40000     // 200*200

#define BQ     32        // queries per block in kernel 1a
#define K1BLOCKS (NQTOT / BQ)   // 225

// dynamic smem layout for kernel 1a (floats):
//  [0,     8224): qs   (32 rows x 257, padded)
//  [8224,  9760): Ws   (16 x 96)
//  [9760, 12832): S    (32 x 96)   offsets(64) | logits->probs(32)
//  [12832,12896): refs (32 x 2)
#define SM_FLOATS 12896
#define SM_BYTES  (SM_FLOATS * 4)

__device__ float  g_fused[(size_t)NQPAD * CDIM];
__device__ int4   g_idx[(size_t)NQTOT * 32];
__device__ float4 g_wc [(size_t)NQTOT * 32];

// ---------------------------------------------------------------------------
// k1a: offsets/logits GEMM + tanh + softmax + sampling-param precompute
// ---------------------------------------------------------------------------
__global__ __launch_bounds__(256) void k1a_params(
    const float* __restrict__ query,
    const float* __restrict__ refpts,
    const float* __restrict__ w_off,
    const float* __restrict__ b_off,
    const float* __restrict__ w_wt,
    const float* __restrict__ b_wt)
{
    extern __shared__ float sm[];
    float* qs   = sm;
    float* Ws   = sm + 8224;
    float* S    = sm + 9760;
    float* refs = sm + 12832;

    const int t = threadIdx.x;
    const int qbase = blockIdx.x * BQ;

    // ---- load 32 query rows + reference points ----
    #pragma unroll
    for (int i = 0; i < 32; i++) {
        int idx = i * 256 + t;
        int r = idx >> 8, k = idx & 255;
        qs[r * 257 + k] = query[(size_t)(qbase + r) * CDIM + k];
    }
    if (t < 64) refs[t] = refpts[(size_t)qbase * 2 + t];

    // ---- GEMM: S[32,96] = q[32,256] @ [w_off | w_wt] ----
    const int rg = t >> 4;
    const int cg = t & 15;
    const int r0 = rg * 2, r1 = r0 + 1;
    const int c0 = cg * 6;

    float acc0[6] = {0,0,0,0,0,0};
    float acc1[6] = {0,0,0,0,0,0};

    for (int kt = 0; kt < 16; kt++) {
        __syncthreads();
        #pragma unroll
        for (int i = 0; i < 6; i++) {
            int idx = i * 256 + t;           // 0..1535
            int k = idx / 96, c = idx - k * 96;
            int kg = kt * 16 + k;
            Ws[idx] = (c < 64) ? w_off[kg * 64 + c] : w_wt[kg * 32 + (c - 64)];
        }
        __syncthreads();
        #pragma unroll
        for (int k = 0; k < 16; k++) {
            float q0 = qs[r0 * 257 + kt * 16 + k];
            float q1 = qs[r1 * 257 + kt * 16 + k];
            const float* wrow = &Ws[k * 96 + c0];
            #pragma unroll
            for (int j = 0; j < 6; j++) {
                float w = wrow[j];
                acc0[j] += q0 * w;
                acc1[j] += q1 * w;
            }
        }
    }

    // epilogue: bias + tanh*0.2 for offsets, bias for logits
    #pragma unroll
    for (int j = 0; j < 6; j++) {
        int c = c0 + j;
        float v0, v1;
        if (c < 64) {
            float b = b_off[c];
            v0 = tanhf(acc0[j] + b) * 0.2f;
            v1 = tanhf(acc1[j] + b) * 0.2f;
        } else {
            float b = b_wt[c - 64];
            v0 = acc0[j] + b;
            v1 = acc1[j] + b;
        }
        S[r0 * 96 + c] = v0;
        S[r1 * 96 + c] = v1;
    }
    __syncthreads();

    // ---- softmax over P per (query, head), in place in S ----
    {
        int q = t >> 3, h = t & 7;
        float* lp = &S[q * 96 + 64 + h * 4];
        float l0 = lp[0], l1 = lp[1], l2 = lp[2], l3 = lp[3];
        float m = fmaxf(fmaxf(l0, l1), fmaxf(l2, l3));
        float e0 = __expf(l0 - m), e1 = __expf(l1 - m);
        float e2 = __expf(l2 - m), e3 = __expf(l3 - m);
        float inv = 1.0f / (e0 + e1 + e2 + e3);
        lp[0] = e0 * inv; lp[1] = e1 * inv;
        lp[2] = e2 * inv; lp[3] = e3 * inv;
    }
    __syncthreads();

    // ---- per-(q, head, p): 4 clamped prescaled offsets + 4 fused weights ----
    #pragma unroll
    for (int it = t; it < BQ * 32; it += 256) {
        int q = it >> 5, pr = it & 31;           // pr = head*4 + p
        float offx = S[q * 96 + pr * 2 + 0];
        float offy = S[q * 96 + pr * 2 + 1];
        float wt   = S[q * 96 + 64 + pr];
        float x = (refs[q * 2 + 0] + offx) * (float)BEV - 0.5f;
        float y = (refs[q * 2 + 1] + offy) * (float)BEV - 0.5f;
        float x0f = floorf(x), y0f = floorf(y);
        int x0 = (int)x0f, y0 = (int)y0f;
        float fx = x - x0f, fy = y - y0f;

        float xv0 = ((unsigned)x0       < (unsigned)BEV) ? 1.f : 0.f;
        float xv1 = ((unsigned)(x0 + 1) < (unsigned)BEV) ? 1.f : 0.f;
        float yv0 = ((unsigned)y0       < (unsigned)BEV) ? 1.f : 0.f;
        float yv1 = ((unsigned)(y0 + 1) < (unsigned)BEV) ? 1.f : 0.f;

        int xc0 = min(max(x0, 0),     BEV - 1);
        int xc1 = min(max(x0 + 1, 0), BEV - 1);
        int yc0 = min(max(y0, 0),     BEV - 1);
        int yc1 = min(max(y0 + 1, 0), BEV - 1);

        int4 id;
        id.x = (yc0 * BEV + xc0) * CDIM;
        id.y = (yc0 * BEV + xc1) * CDIM;
        id.z = (yc1 * BEV + xc0) * CDIM;
        id.w = (yc1 * BEV + xc1) * CDIM;

        float gx1 = 1.0f - fx, gy1 = 1.0f - fy;
        float4 w;
        w.x = wt * gx1 * gy1 * (xv0 * yv0);
        w.y = wt * fx  * gy1 * (xv1 * yv0);
        w.z = wt * gx1 * fy  * (xv0 * yv1);
        w.w = wt * fx  * fy  * (xv1 * yv1);

        g_idx[(size_t)qbase * 32 + it] = id;
        g_wc [(size_t)qbase * 32 + it] = w;
    }
}

// ---------------------------------------------------------------------------
// k1b: bilinear sampling + weighted sum over P. One block per query.
// block = 256 threads = 8 heads x 32 lanes; 16 gathers per thread.
// ---------------------------------------------------------------------------
__global__ __launch_bounds__(256) void k1b_sample(
    const float* __restrict__ memory)
{
    __shared__ int4   sIdx[32];
    __shared__ float4 sWc[32];

    const int t = threadIdx.x;
    const int q = blockIdx.x;

    if (t < 32) {
        sIdx[t] = g_idx[(size_t)q * 32 + t];
        sWc[t]  = g_wc [(size_t)q * 32 + t];
    }
    __syncthreads();

    const int head = t >> 5;          // channel = t
    const float* memb = memory + (size_t)(q / NPERB) * HW * CDIM + t;

    float acc = 0.0f;
    #pragma unroll
    for (int p = 0; p < NPTS; p++) {
        int ii = head * 4 + p;
        int4   id = sIdx[ii];       // warp-uniform broadcast
        float4 w  = sWc[ii];
        float v00 = __ldg(memb + id.x);
        float v01 = __ldg(memb + id.y);
        float v10 = __ldg(memb + id.z);
        float v11 = __ldg(memb + id.w);
        acc += w.x * v00 + w.y * v01 + w.z * v10 + w.w * v11;
    }
    g_fused[(size_t)q * CDIM + t] = acc;
}

// ---------------------------------------------------------------------------
// k2: out[7200,256] = g_fused @ w_out[256,256] + b_out
// 128x64 tile, 256 threads, 8x4 per-thread micro-tile (FMA-dominant)
// ---------------------------------------------------------------------------
__global__ __launch_bounds__(256) void k2_outproj(
    const float* __restrict__ w_out,
    const float* __restrict__ b_out,
    float* __restrict__ out)
{
    __shared__ float As[16][132];   // k-major, padded
    __shared__ float Bs[16][64];

    const int t  = threadIdx.x;
    const int tx = t & 15, ty = t >> 4;
    const int bm = blockIdx.y, bn = blockIdx.x;

    const int arow = t >> 1;          // 0..127 (m within tile)
    const int ak   = (t & 1) * 8;     // 0 or 8 (k base)
    const int brow = t >> 4;          // 0..15
    const int bcol = (t & 15) * 4;    // 0..60

    const size_t mbase = (size_t)bm * 128;

    float acc[8][4] = {};

    for (int kt = 0; kt < 16; kt++) {
        const float* arp = &g_fused[(mbase + arow) * CDIM + kt * 16 + ak];
        float4 a0 = *(const float4*)(arp);
        float4 a1 = *(const float4*)(arp + 4);
        As[ak + 0][arow] = a0.x;
        As[ak + 1][arow] = a0.y;
        As[ak + 2][arow] = a0.z;
        As[ak + 3][arow] = a0.w;
        As[ak + 4][arow] = a1.x;
        As[ak + 5][arow] = a1.y;
        As[ak + 6][arow] = a1.z;
        As[ak + 7][arow] = a1.w;

        float4 bv = *(const float4*)&w_out[(size_t)(kt * 16 + brow) * CDIM + bn * 64 + bcol];
        *(float4*)&Bs[brow][bcol] = bv;

        __syncthreads();
        #pragma unroll
        for (int k = 0; k < 16; k++) {
            float4 aa0 = *(const float4*)&As[k][ty * 8];
            float4 aa1 = *(const float4*)&As[k][ty * 8 + 4];
            float4 b4  = *(const float4*)&Bs[k][tx * 4];
            float a8[8] = {aa0.x, aa0.y, aa0.z, aa0.w, aa1.x, aa1.y, aa1.z, aa1.w};
            float bb[4] = {b4.x, b4.y, b4.z, b4.w};
            #pragma unroll
            for (int i = 0; i < 8; i++)
                #pragma unroll
                for (int j = 0; j < 4; j++)
                    acc[i][j] += a8[i] * bb[j];
        }
        __syncthreads();
    }

    const int ncol = bn * 64 + tx * 4;
    float4 bias = *(const float4*)&b_out[ncol];
    #pragma unroll
    for (int i = 0; i < 8; i++) {
        size_t m = mbase + ty * 8 + i;
        if (m < NQTOT) {
            float4 v;
            v.x = acc[i][0] + bias.x;
            v.y = acc[i][1] + bias.y;
            v.z = acc[i][2] + bias.z;
            v.w = acc[i][3] + bias.w;
            *(float4*)&out[m * CDIM + ncol] = v;
        }
    }
}

extern "C" void kernel_launch(void* const* d_in, const int* in_sizes, int n_in,
                              void* d_out, int out_size)
{
    const float* query  = (const float*)d_in[0];
    const float* memory = (const float*)d_in[1];
    const float* refpts = (const float*)d_in[2];
    const float* w_off  = (const float*)d_in[3];
    const float* b_off  = (const float*)d_in[4];
    const float* w_wt   = (const float*)d_in[5];
    const float* b_wt   = (const float*)d_in[6];
    const float* w_out  = (const float*)d_in[7];
    const float* b_out  = (const float*)d_in[8];
    float* out = (float*)d_out;

    cudaFuncSetAttribute(k1a_params,
                         cudaFuncAttributeMaxDynamicSharedMemorySize, SM_BYTES);

    k1a_params<<<K1BLOCKS, 256, SM_BYTES>>>(
        query, refpts, w_off, b_off, w_wt, b_wt);

    k1b_sample<<<NQTOT, 256>>>(memory);

    dim3 g2(CDIM / 64, NQPAD / 128);   // (4, 57)
    k2_outproj<<<g2, 256>>>(w_out, b_out, out);
}